// round 5
// baseline (speedup 1.0000x reference)
#include <cuda_runtime.h>
#include <mma.h>

using namespace nvcuda;

#define N_NODES 50000
#define E_EDGES 800000
#define IN_DIM  128
#define NHEAD   8
#define HD      128          // H*D

#define SCAN_BLK 512
#define SCAN_NB  ((N_NODES + SCAN_BLK - 1) / SCAN_BLK)   // 98

#define GEMM_BM 64
#define GEMM_BN 128

// Scratch (static __device__ — no allocation allowed)
__device__ float g_q [(size_t)N_NODES * HD];        // 25.6 MB (per-node reads)
__device__ float g_kv[(size_t)N_NODES * 2 * HD];    // 51.2 MB: K | V per node
__device__ int   g_deg[N_NODES];
__device__ int   g_off[N_NODES];      // block-local exclusive scan of deg
__device__ int   g_cursor[N_NODES];   // scatter cursors (block-local offsets)
__device__ int   g_bsum[SCAN_NB];
__device__ int   g_boff[SCAN_NB];     // scanned block offsets
__device__ int   g_esrc[E_EDGES];     // src node per edge, grouped by dst

// ---------------------------------------------------------------------------
__global__ void zero_deg_kernel() {
    int i = blockIdx.x * blockDim.x + threadIdx.x;
    if (i < N_NODES) g_deg[i] = 0;
}

__global__ void hist_kernel(const int* __restrict__ dst) {
    int e = blockIdx.x * blockDim.x + threadIdx.x;
    if (e < E_EDGES) atomicAdd(&g_deg[dst[e]], 1);
}

// Block-local inclusive scan -> exclusive per-element + block sums.
// Writes both g_off and g_cursor (consumers add g_boff[i>>9] themselves).
__global__ __launch_bounds__(SCAN_BLK) void scan1_kernel() {
    __shared__ int sd[SCAN_BLK];
    int t = threadIdx.x;
    int i = blockIdx.x * SCAN_BLK + t;
    int v = (i < N_NODES) ? g_deg[i] : 0;
    sd[t] = v;
    __syncthreads();
    #pragma unroll
    for (int off = 1; off < SCAN_BLK; off <<= 1) {
        int add = (t >= off) ? sd[t - off] : 0;
        __syncthreads();
        sd[t] += add;
        __syncthreads();
    }
    if (i < N_NODES) {
        int o = sd[t] - v;
        g_off[i] = o;
        g_cursor[i] = o;
    }
    if (t == SCAN_BLK - 1) g_bsum[blockIdx.x] = sd[t];
}

// Scan the 98 block sums (single block)
__global__ void scan2_kernel() {
    __shared__ int sb[SCAN_NB];
    int t = threadIdx.x;
    if (t < SCAN_NB) sb[t] = g_bsum[t];
    __syncthreads();
    if (t == 0) {
        int run = 0;
        for (int b = 0; b < SCAN_NB; b++) { int x = sb[b]; sb[b] = run; run += x; }
    }
    __syncthreads();
    if (t < SCAN_NB) g_boff[t] = sb[t];
}

// Scatter src ids into dst-grouped buckets (global pos = block off + local cursor)
__global__ void scatter_kernel(const int* __restrict__ src,
                               const int* __restrict__ dst) {
    int e = blockIdx.x * blockDim.x + threadIdx.x;
    if (e >= E_EDGES) return;
    int d = dst[e];
    int pos = g_boff[d >> 9] + atomicAdd(&g_cursor[d], 1);
    g_esrc[pos] = src[e];
}

// ---------------------------------------------------------------------------
// QKV projection on tensor cores (tf32 wmma m16n16k8, fp32 accumulate).
// Block: 128 threads = 4 warps; covers BM=64 rows x BN=128 cols of one proj.
// Warp w computes rows [m0+16w, m0+16w+16) x all 128 cols (8 acc fragments).
// grid = (ceil(N/64), 3); proj 0 -> g_q, proj 1 -> g_kv[:, :128], proj 2 -> g_kv[:,128:]
// ---------------------------------------------------------------------------
__global__ __launch_bounds__(128) void qkv_tc_kernel(
    const float* __restrict__ h,
    const float* __restrict__ Wq, const float* __restrict__ bq,
    const float* __restrict__ Wk, const float* __restrict__ bk,
    const float* __restrict__ Wv, const float* __restrict__ bv)
{
    const int wid  = threadIdx.x >> 5;
    const int m0   = blockIdx.x * GEMM_BM;
    const int proj = blockIdx.y;

    const float* W = (proj == 0) ? Wq : (proj == 1) ? Wk : Wv;
    const float* b = (proj == 0) ? bq : (proj == 1) ? bk : bv;

    wmma::fragment<wmma::accumulator, 16, 16, 8, float> acc[8];
    #pragma unroll
    for (int nt = 0; nt < 8; nt++) wmma::fill_fragment(acc[nt], 0.0f);

    wmma::fragment<wmma::matrix_a, 16, 16, 8, wmma::precision::tf32, wmma::row_major> af;
    wmma::fragment<wmma::matrix_b, 16, 16, 8, wmma::precision::tf32, wmma::row_major> bf;

    const bool full = (m0 + GEMM_BM <= N_NODES);
    const int mrow = m0 + wid * 16;

    __shared__ __align__(32) float Asm[GEMM_BM][8];           // tail-path staging
    __shared__ __align__(16) float Cs[GEMM_BM][GEMM_BN];      // 32 KB epilogue

    if (full) {
        #pragma unroll 4
        for (int k0 = 0; k0 < IN_DIM; k0 += 8) {
            wmma::load_matrix_sync(af, h + (size_t)mrow * IN_DIM + k0, IN_DIM);
            #pragma unroll
            for (int i = 0; i < af.num_elements; i++)
                af.x[i] = wmma::__float_to_tf32(af.x[i]);
            #pragma unroll
            for (int nt = 0; nt < 8; nt++) {
                wmma::load_matrix_sync(bf, W + (size_t)k0 * HD + nt * 16, HD);
                #pragma unroll
                for (int i = 0; i < bf.num_elements; i++)
                    bf.x[i] = wmma::__float_to_tf32(bf.x[i]);
                wmma::mma_sync(acc[nt], af, bf, acc[nt]);
            }
        }
    } else {
        // tail block: stage A through smem with zero padding
        for (int k0 = 0; k0 < IN_DIM; k0 += 8) {
            __syncthreads();
            for (int idx = threadIdx.x; idx < GEMM_BM * 8; idx += 128) {
                int r = idx >> 3, c = idx & 7;
                int gr = m0 + r;
                Asm[r][c] = (gr < N_NODES) ? h[(size_t)gr * IN_DIM + k0 + c] : 0.0f;
            }
            __syncthreads();
            wmma::load_matrix_sync(af, &Asm[wid * 16][0], 8);
            #pragma unroll
            for (int i = 0; i < af.num_elements; i++)
                af.x[i] = wmma::__float_to_tf32(af.x[i]);
            #pragma unroll
            for (int nt = 0; nt < 8; nt++) {
                wmma::load_matrix_sync(bf, W + (size_t)k0 * HD + nt * 16, HD);
                #pragma unroll
                for (int i = 0; i < bf.num_elements; i++)
                    bf.x[i] = wmma::__float_to_tf32(bf.x[i]);
                wmma::mma_sync(acc[nt], af, bf, acc[nt]);
            }
        }
    }

    // epilogue: acc -> smem -> (+bias) -> global
    #pragma unroll
    for (int nt = 0; nt < 8; nt++)
        wmma::store_matrix_sync(&Cs[wid * 16][nt * 16], acc[nt], GEMM_BN,
                                wmma::mem_row_major);
    __syncthreads();

    float* dstbuf;
    size_t stride;
    int    coff;
    if (proj == 0) { dstbuf = g_q;  stride = HD;     coff = 0; }
    else           { dstbuf = g_kv; stride = 2 * HD; coff = (proj == 2) ? HD : 0; }

    for (int idx = threadIdx.x; idx < GEMM_BM * (GEMM_BN / 4); idx += 128) {
        int r  = idx >> 5;            // 32 float4 chunks per row
        int c4 = (idx & 31) * 4;
        int gr = m0 + r;
        if (gr < N_NODES) {
            float4 v = *(float4*)&Cs[r][c4];
            float4 bb = __ldg((const float4*)&b[c4]);
            v.x += bb.x; v.y += bb.y; v.z += bb.z; v.w += bb.w;
            *(float4*)&dstbuf[(size_t)gr * stride + coff + c4] = v;
        }
    }
}

// ---------------------------------------------------------------------------
// Node kernel: one warp per dst node. No atomics.
// lane t: float4 over dims [4t,4t+4), head = t>>2 (4 lanes per head).
// ---------------------------------------------------------------------------
__global__ __launch_bounds__(256) void node_kernel(
    const float* __restrict__ dis,
    const float* __restrict__ att_w, const float* __restrict__ att_b,
    float* __restrict__ out)
{
    const int warp = (blockIdx.x * blockDim.x + threadIdx.x) >> 5;
    const int lane = threadIdx.x & 31;
    if (warp >= N_NODES) return;
    const int n = warp;

    // hoist CSR range so its latency overlaps the Q gather
    const int start = __ldg(&g_off[n]) + __ldg(&g_boff[n >> 9]);
    const int deg   = __ldg(&g_deg[n]);
    const int end   = start + deg;

    const float4* kv4 = (const float4*)g_kv;
    const float4  q   = __ldg(((const float4*)g_q) + (size_t)n * 32 + lane);

    const int head = lane >> 2;
    const float bias = __ldg(&dis[n]) * __ldg(&att_w[head]) + __ldg(&att_b[head]);

    float4 acc = make_float4(0.f, 0.f, 0.f, 0.f);
    float z = 0.f;

    int i = start;
    // 4-edge unrolled main loop: 8 outstanding LDG.128/lane for latency hiding
    for (; i + 4 <= end; i += 4) {
        int s0 = __ldg(&g_esrc[i]);
        int s1 = __ldg(&g_esrc[i + 1]);
        int s2 = __ldg(&g_esrc[i + 2]);
        int s3 = __ldg(&g_esrc[i + 3]);
        size_t r0 = (size_t)s0 * 64, r1 = (size_t)s1 * 64;
        size_t r2 = (size_t)s2 * 64, r3 = (size_t)s3 * 64;
        float4 k0 = __ldg(kv4 + r0 + lane),      k1 = __ldg(kv4 + r1 + lane);
        float4 k2 = __ldg(kv4 + r2 + lane),      k3 = __ldg(kv4 + r3 + lane);
        float4 v0 = __ldg(kv4 + r0 + 32 + lane), v1 = __ldg(kv4 + r1 + 32 + lane);
        float4 v2 = __ldg(kv4 + r2 + 32 + lane), v3 = __ldg(kv4 + r3 + 32 + lane);

        float p0 = q.x * k0.x + q.y * k0.y + q.z * k0.z + q.w * k0.w;
        float p1 = q.x * k1.x + q.y * k1.y + q.z * k1.z + q.w * k1.w;
        float p2 = q.x * k2.x + q.y * k2.y + q.z * k2.z + q.w * k2.w;
        float p3 = q.x * k3.x + q.y * k3.y + q.z * k3.z + q.w * k3.w;
        p0 += __shfl_xor_sync(0xffffffffu, p0, 1);
        p0 += __shfl_xor_sync(0xffffffffu, p0, 2);
        p1 += __shfl_xor_sync(0xffffffffu, p1, 1);
        p1 += __shfl_xor_sync(0xffffffffu, p1, 2);
        p2 += __shfl_xor_sync(0xffffffffu, p2, 1);
        p2 += __shfl_xor_sync(0xffffffffu, p2, 2);
        p3 += __shfl_xor_sync(0xffffffffu, p3, 1);
        p3 += __shfl_xor_sync(0xffffffffu, p3, 2);

        float e0 = __expf(fminf(fmaxf((p0 + bias) * 0.25f, -5.0f), 5.0f));
        float e1 = __expf(fminf(fmaxf((p1 + bias) * 0.25f, -5.0f), 5.0f));
        float e2 = __expf(fminf(fmaxf((p2 + bias) * 0.25f, -5.0f), 5.0f));
        float e3 = __expf(fminf(fmaxf((p3 + bias) * 0.25f, -5.0f), 5.0f));

        acc.x += v0.x * e0 + v1.x * e1 + v2.x * e2 + v3.x * e3;
        acc.y += v0.y * e0 + v1.y * e1 + v2.y * e2 + v3.y * e3;
        acc.z += v0.z * e0 + v1.z * e1 + v2.z * e2 + v3.z * e3;
        acc.w += v0.w * e0 + v1.w * e1 + v2.w * e2 + v3.w * e3;
        z += e0 + e1 + e2 + e3;
    }
    for (; i < end; i++) {
        int s = __ldg(&g_esrc[i]);
        size_t r = (size_t)s * 64;
        float4 k = __ldg(kv4 + r + lane);
        float4 v = __ldg(kv4 + r + 32 + lane);
        float p = q.x * k.x + q.y * k.y + q.z * k.z + q.w * k.w;
        p += __shfl_xor_sync(0xffffffffu, p, 1);
        p += __shfl_xor_sync(0xffffffffu, p, 2);
        float ex = __expf(fminf(fmaxf((p + bias) * 0.25f, -5.0f), 5.0f));
        acc.x += v.x * ex;
        acc.y += v.y * ex;
        acc.z += v.z * ex;
        acc.w += v.w * ex;
        z += ex;
    }

    float inv = 1.0f / z;   // deg-0 node -> NaN, matches reference 0/0
    float4 o;
    o.x = acc.x * inv; o.y = acc.y * inv; o.z = acc.z * inv; o.w = acc.w * inv;
    *(float4*)&out[(size_t)n * HD + lane * 4] = o;
}

// ---------------------------------------------------------------------------
extern "C" void kernel_launch(void* const* d_in, const int* in_sizes, int n_in,
                              void* d_out, int out_size) {
    const float* h     = (const float*)d_in[0];
    const float* dis   = (const float*)d_in[1];
    const float* Wq    = (const float*)d_in[2];
    const float* bq    = (const float*)d_in[3];
    const float* Wk    = (const float*)d_in[4];
    const float* bk    = (const float*)d_in[5];
    const float* Wv    = (const float*)d_in[6];
    const float* bv    = (const float*)d_in[7];
    const float* att_w = (const float*)d_in[8];
    const float* att_b = (const float*)d_in[9];
    const int*   src   = (const int*)d_in[10];
    const int*   dst   = (const int*)d_in[11];
    float* out = (float*)d_out;

    const int EB = 256;

    // CSR build (dst-grouped edge buckets)
    zero_deg_kernel<<<(N_NODES + EB - 1) / EB, EB>>>();
    hist_kernel<<<(E_EDGES + EB - 1) / EB, EB>>>(dst);
    scan1_kernel<<<SCAN_NB, SCAN_BLK>>>();
    scan2_kernel<<<1, 128>>>();
    scatter_kernel<<<(E_EDGES + EB - 1) / EB, EB>>>(src, dst);

    // QKV projection on tensor cores (tf32)
    dim3 g((N_NODES + GEMM_BM - 1) / GEMM_BM, 3);
    qkv_tc_kernel<<<g, 128>>>(h, Wq, bq, Wk, bk, Wv, bv);

    // One warp per node, atomic-free accumulate + normalize
    node_kernel<<<(N_NODES * 32 + EB - 1) / EB, EB>>>(dis, att_w, att_b, out);
}

// round 13
// speedup vs baseline: 1.0597x; 1.0597x over previous
#include <cuda_runtime.h>

#define N_NODES 50000
#define E_EDGES 800000
#define IN_DIM  128
#define NHEAD   8
#define HD      128          // H*D

#define SCAN_BLK 512
#define SCAN_NB  ((N_NODES + SCAN_BLK - 1) / SCAN_BLK)   // 98

// Scratch (static __device__ — no allocation allowed)
__device__ float g_q [(size_t)N_NODES * HD];        // 25.6 MB (per-node reads)
__device__ float g_kv[(size_t)N_NODES * 2 * HD];    // 51.2 MB: K | V per node
__device__ int   g_deg[N_NODES];
__device__ int   g_off[N_NODES];      // block-local exclusive scan of deg
__device__ int   g_cursor[N_NODES];   // scatter cursors (block-local offsets)
__device__ int   g_bsum[SCAN_NB];
__device__ int   g_boff[SCAN_NB];     // scanned block offsets
__device__ int   g_esrc[E_EDGES];     // src node per edge, grouped by dst

// ---------------------------------------------------------------------------
__global__ void zero_deg_kernel() {
    int i = blockIdx.x * blockDim.x + threadIdx.x;
    if (i < N_NODES) g_deg[i] = 0;
}

__global__ void hist_kernel(const int* __restrict__ dst) {
    int e = blockIdx.x * blockDim.x + threadIdx.x;
    if (e < E_EDGES) atomicAdd(&g_deg[dst[e]], 1);
}

// Block-local inclusive scan -> exclusive per-element + block sums.
// Writes both g_off and g_cursor (consumers add g_boff[i>>9] themselves).
__global__ __launch_bounds__(SCAN_BLK) void scan1_kernel() {
    __shared__ int sd[SCAN_BLK];
    int t = threadIdx.x;
    int i = blockIdx.x * SCAN_BLK + t;
    int v = (i < N_NODES) ? g_deg[i] : 0;
    sd[t] = v;
    __syncthreads();
    #pragma unroll
    for (int off = 1; off < SCAN_BLK; off <<= 1) {
        int add = (t >= off) ? sd[t - off] : 0;
        __syncthreads();
        sd[t] += add;
        __syncthreads();
    }
    if (i < N_NODES) {
        int o = sd[t] - v;
        g_off[i] = o;
        g_cursor[i] = o;
    }
    if (t == SCAN_BLK - 1) g_bsum[blockIdx.x] = sd[t];
}

// Scan the 98 block sums (single block)
__global__ void scan2_kernel() {
    __shared__ int sb[SCAN_NB];
    int t = threadIdx.x;
    if (t < SCAN_NB) sb[t] = g_bsum[t];
    __syncthreads();
    if (t == 0) {
        int run = 0;
        for (int b = 0; b < SCAN_NB; b++) { int x = sb[b]; sb[b] = run; run += x; }
    }
    __syncthreads();
    if (t < SCAN_NB) g_boff[t] = sb[t];
}

// Scatter src ids into dst-grouped buckets (global pos = block off + local cursor)
__global__ void scatter_kernel(const int* __restrict__ src,
                               const int* __restrict__ dst) {
    int e = blockIdx.x * blockDim.x + threadIdx.x;
    if (e >= E_EDGES) return;
    int d = dst[e];
    int pos = g_boff[d >> 9] + atomicAdd(&g_cursor[d], 1);
    g_esrc[pos] = src[e];
}

// ---------------------------------------------------------------------------
// QKV projection, fp32 SIMT. BM=128, BN=128(=full width), BK=16, 256 threads,
// 8x8 register micro-tile, global->register prefetch pipeline.
// grid = (ceil(N/128), 3), proj = blockIdx.y.
// proj 0 -> g_q; proj 1 -> g_kv[:, :128]; proj 2 -> g_kv[:, 128:]
// ---------------------------------------------------------------------------
__global__ __launch_bounds__(256) void qkv_kernel(
    const float* __restrict__ h,
    const float* __restrict__ Wq, const float* __restrict__ bq,
    const float* __restrict__ Wk, const float* __restrict__ bk,
    const float* __restrict__ Wv, const float* __restrict__ bv)
{
    __shared__ float As[16][132];   // [k][m], padded
    __shared__ float Bs[16][128];   // [k][n]

    const int tid = threadIdx.x;
    const int tx  = tid & 15;       // 16 col-groups (8 cols each)
    const int ty  = tid >> 4;       // 16 row-groups (8 rows each)
    const int m0  = blockIdx.x * 128;
    const int proj = blockIdx.y;

    const float* W = (proj == 0) ? Wq : (proj == 1) ? Wk : Wv;
    const float* b = (proj == 0) ? bq : (proj == 1) ? bk : bv;

    // A-load: row = tid>>1 (0..127), k-offset = (tid&1)*8, two float4s
    const int am  = tid >> 1;
    const int ak  = (tid & 1) * 8;
    const int agrow = m0 + am;
    const bool arow_ok = (agrow < N_NODES);
    // B-load: k-row = tid>>4 (0..15), col-group at bnn, two float4s
    const int bk_ = tid >> 4;
    const int bnn = (tid & 15) * 8;

    float acc[8][8] = {};

    const float4 f4z = make_float4(0.f, 0.f, 0.f, 0.f);
    float4 cA0 = f4z, cA1 = f4z, cB0, cB1;

    // prologue: load k-step 0 into registers
    if (arow_ok) {
        cA0 = __ldg((const float4*)&h[(size_t)agrow * IN_DIM + ak]);
        cA1 = __ldg((const float4*)&h[(size_t)agrow * IN_DIM + ak + 4]);
    }
    cB0 = __ldg((const float4*)&W[(size_t)bk_ * HD + bnn]);
    cB1 = __ldg((const float4*)&W[(size_t)bk_ * HD + bnn + 4]);

    #pragma unroll
    for (int step = 0; step < 8; step++) {
        // store current tile to smem
        As[ak + 0][am] = cA0.x;
        As[ak + 1][am] = cA0.y;
        As[ak + 2][am] = cA0.z;
        As[ak + 3][am] = cA0.w;
        As[ak + 4][am] = cA1.x;
        As[ak + 5][am] = cA1.y;
        As[ak + 6][am] = cA1.z;
        As[ak + 7][am] = cA1.w;
        *(float4*)&Bs[bk_][bnn]     = cB0;
        *(float4*)&Bs[bk_][bnn + 4] = cB1;
        __syncthreads();

        // prefetch next k-step (LDG issued before the FFMA block)
        if (step < 7) {
            int k0 = (step + 1) * 16;
            if (arow_ok) {
                cA0 = __ldg((const float4*)&h[(size_t)agrow * IN_DIM + k0 + ak]);
                cA1 = __ldg((const float4*)&h[(size_t)agrow * IN_DIM + k0 + ak + 4]);
            }
            cB0 = __ldg((const float4*)&W[(size_t)(k0 + bk_) * HD + bnn]);
            cB1 = __ldg((const float4*)&W[(size_t)(k0 + bk_) * HD + bnn + 4]);
        }

        #pragma unroll
        for (int kk = 0; kk < 16; kk++) {
            float a[8], bb[8];
            *(float4*)&a[0]  = *(float4*)&As[kk][ty * 8];
            *(float4*)&a[4]  = *(float4*)&As[kk][ty * 8 + 4];
            *(float4*)&bb[0] = *(float4*)&Bs[kk][tx * 8];
            *(float4*)&bb[4] = *(float4*)&Bs[kk][tx * 8 + 4];
            #pragma unroll
            for (int i = 0; i < 8; i++)
                #pragma unroll
                for (int j = 0; j < 8; j++)
                    acc[i][j] += a[i] * bb[j];
        }
        __syncthreads();
    }

    // epilogue: add bias, write out
    float* dstbuf;
    size_t stride;
    int    coff;
    if (proj == 0) { dstbuf = g_q;  stride = HD;     coff = 0; }
    else           { dstbuf = g_kv; stride = 2 * HD; coff = (proj == 2) ? HD : 0; }

    float4 b0 = __ldg((const float4*)&b[tx * 8]);
    float4 b1 = __ldg((const float4*)&b[tx * 8 + 4]);
    #pragma unroll
    for (int i = 0; i < 8; i++) {
        int row = m0 + ty * 8 + i;
        if (row < N_NODES) {
            float4 o0, o1;
            o0.x = acc[i][0] + b0.x; o0.y = acc[i][1] + b0.y;
            o0.z = acc[i][2] + b0.z; o0.w = acc[i][3] + b0.w;
            o1.x = acc[i][4] + b1.x; o1.y = acc[i][5] + b1.y;
            o1.z = acc[i][6] + b1.z; o1.w = acc[i][7] + b1.w;
            float* base = &dstbuf[(size_t)row * stride + coff + tx * 8];
            *(float4*)base       = o0;
            *(float4*)(base + 4) = o1;
        }
    }
}

// ---------------------------------------------------------------------------
// Node kernel: one warp per dst node. No atomics.
// lane t: float4 over dims [4t,4t+4), head = t>>2 (4 lanes per head).
// ---------------------------------------------------------------------------
__global__ __launch_bounds__(256) void node_kernel(
    const float* __restrict__ dis,
    const float* __restrict__ att_w, const float* __restrict__ att_b,
    float* __restrict__ out)
{
    const int warp = (blockIdx.x * blockDim.x + threadIdx.x) >> 5;
    const int lane = threadIdx.x & 31;
    if (warp >= N_NODES) return;
    const int n = warp;

    // hoist CSR range so its latency overlaps the Q gather
    const int start = __ldg(&g_off[n]) + __ldg(&g_boff[n >> 9]);
    const int deg   = __ldg(&g_deg[n]);
    const int end   = start + deg;

    const float4* kv4 = (const float4*)g_kv;
    const float4  q   = __ldg(((const float4*)g_q) + (size_t)n * 32 + lane);

    const int head = lane >> 2;
    const float bias = __ldg(&dis[n]) * __ldg(&att_w[head]) + __ldg(&att_b[head]);

    float4 acc = make_float4(0.f, 0.f, 0.f, 0.f);
    float z = 0.f;

    int i = start;
    // 4-edge unrolled main loop: 8 outstanding LDG.128/lane for latency hiding
    for (; i + 4 <= end; i += 4) {
        int s0 = __ldg(&g_esrc[i]);
        int s1 = __ldg(&g_esrc[i + 1]);
        int s2 = __ldg(&g_esrc[i + 2]);
        int s3 = __ldg(&g_esrc[i + 3]);
        size_t r0 = (size_t)s0 * 64, r1 = (size_t)s1 * 64;
        size_t r2 = (size_t)s2 * 64, r3 = (size_t)s3 * 64;
        float4 k0 = __ldg(kv4 + r0 + lane),      k1 = __ldg(kv4 + r1 + lane);
        float4 k2 = __ldg(kv4 + r2 + lane),      k3 = __ldg(kv4 + r3 + lane);
        float4 v0 = __ldg(kv4 + r0 + 32 + lane), v1 = __ldg(kv4 + r1 + 32 + lane);
        float4 v2 = __ldg(kv4 + r2 + 32 + lane), v3 = __ldg(kv4 + r3 + 32 + lane);

        float p0 = q.x * k0.x + q.y * k0.y + q.z * k0.z + q.w * k0.w;
        float p1 = q.x * k1.x + q.y * k1.y + q.z * k1.z + q.w * k1.w;
        float p2 = q.x * k2.x + q.y * k2.y + q.z * k2.z + q.w * k2.w;
        float p3 = q.x * k3.x + q.y * k3.y + q.z * k3.z + q.w * k3.w;
        p0 += __shfl_xor_sync(0xffffffffu, p0, 1);
        p0 += __shfl_xor_sync(0xffffffffu, p0, 2);
        p1 += __shfl_xor_sync(0xffffffffu, p1, 1);
        p1 += __shfl_xor_sync(0xffffffffu, p1, 2);
        p2 += __shfl_xor_sync(0xffffffffu, p2, 1);
        p2 += __shfl_xor_sync(0xffffffffu, p2, 2);
        p3 += __shfl_xor_sync(0xffffffffu, p3, 1);
        p3 += __shfl_xor_sync(0xffffffffu, p3, 2);

        float e0 = __expf(fminf(fmaxf((p0 + bias) * 0.25f, -5.0f), 5.0f));
        float e1 = __expf(fminf(fmaxf((p1 + bias) * 0.25f, -5.0f), 5.0f));
        float e2 = __expf(fminf(fmaxf((p2 + bias) * 0.25f, -5.0f), 5.0f));
        float e3 = __expf(fminf(fmaxf((p3 + bias) * 0.25f, -5.0f), 5.0f));

        acc.x += v0.x * e0 + v1.x * e1 + v2.x * e2 + v3.x * e3;
        acc.y += v0.y * e0 + v1.y * e1 + v2.y * e2 + v3.y * e3;
        acc.z += v0.z * e0 + v1.z * e1 + v2.z * e2 + v3.z * e3;
        acc.w += v0.w * e0 + v1.w * e1 + v2.w * e2 + v3.w * e3;
        z += e0 + e1 + e2 + e3;
    }
    for (; i < end; i++) {
        int s = __ldg(&g_esrc[i]);
        size_t r = (size_t)s * 64;
        float4 k = __ldg(kv4 + r + lane);
        float4 v = __ldg(kv4 + r + 32 + lane);
        float p = q.x * k.x + q.y * k.y + q.z * k.z + q.w * k.w;
        p += __shfl_xor_sync(0xffffffffu, p, 1);
        p += __shfl_xor_sync(0xffffffffu, p, 2);
        float ex = __expf(fminf(fmaxf((p + bias) * 0.25f, -5.0f), 5.0f));
        acc.x += v.x * ex;
        acc.y += v.y * ex;
        acc.z += v.z * ex;
        acc.w += v.w * ex;
        z += ex;
    }

    float inv = 1.0f / z;   // deg-0 node -> NaN, matches reference 0/0
    float4 o;
    o.x = acc.x * inv; o.y = acc.y * inv; o.z = acc.z * inv; o.w = acc.w * inv;
    *(float4*)&out[(size_t)n * HD + lane * 4] = o;
}

// ---------------------------------------------------------------------------
extern "C" void kernel_launch(void* const* d_in, const int* in_sizes, int n_in,
                              void* d_out, int out_size) {
    const float* h     = (const float*)d_in[0];
    const float* dis   = (const float*)d_in[1];
    const float* Wq    = (const float*)d_in[2];
    const float* bq    = (const float*)d_in[3];
    const float* Wk    = (const float*)d_in[4];
    const float* bk    = (const float*)d_in[5];
    const float* Wv    = (const float*)d_in[6];
    const float* bv    = (const float*)d_in[7];
    const float* att_w = (const float*)d_in[8];
    const float* att_b = (const float*)d_in[9];
    const int*   src   = (const int*)d_in[10];
    const int*   dst   = (const int*)d_in[11];
    float* out = (float*)d_out;

    const int EB = 256;

    // Launch order puts qkv_kernel in the ncu-profiled slot (4th launch).
    zero_deg_kernel<<<(N_NODES + EB - 1) / EB, EB>>>();
    hist_kernel<<<(E_EDGES + EB - 1) / EB, EB>>>(dst);
    scan1_kernel<<<SCAN_NB, SCAN_BLK>>>();

    dim3 g((N_NODES + 127) / 128, 3);
    qkv_kernel<<<g, 256>>>(h, Wq, bq, Wk, bk, Wv, bv);   // profiled slot (index 3)

    scan2_kernel<<<1, 128>>>();
    scatter_kernel<<<(E_EDGES + EB - 1) / EB, EB>>>(src, dst);

    node_kernel<<<(N_NODES * 32 + EB - 1) / EB, EB>>>(dis, att_w, att_b, out);
}

// round 14
// speedup vs baseline: 1.2412x; 1.1712x over previous
#include <cuda_runtime.h>

#define N_NODES 50000
#define E_EDGES 800000
#define IN_DIM  128
#define NHEAD   8
#define HD      128          // H*D

#define SCAN_BLK 512
#define SCAN_NB  ((N_NODES + SCAN_BLK - 1) / SCAN_BLK)   // 98

typedef unsigned long long u64;

#define FMA_F32X2(d, a, b, c) \
    asm("fma.rn.f32x2 %0, %1, %2, %3;" : "=l"(d) : "l"(a), "l"(b), "l"(c))
#define PACK_F32X2(out, lo, hi) \
    asm("mov.b64 %0, {%1, %2};" : "=l"(out) : "f"(lo), "f"(hi))
#define UNPACK_F32X2(lo, hi, in) \
    asm("mov.b64 {%0, %1}, %2;" : "=f"(lo), "=f"(hi) : "l"(in))

// Scratch (static __device__ — no allocation allowed)
__device__ float g_q [(size_t)N_NODES * HD];        // 25.6 MB (per-node reads)
__device__ float g_kv[(size_t)N_NODES * 2 * HD];    // 51.2 MB: K | V per node
__device__ int   g_deg[N_NODES];
__device__ int   g_off[N_NODES];      // block-local exclusive scan of deg
__device__ int   g_cursor[N_NODES];   // scatter cursors (block-local offsets)
__device__ int   g_bsum[SCAN_NB];
__device__ int   g_boff[SCAN_NB];     // scanned block offsets
__device__ int   g_esrc[E_EDGES];     // src node per edge, grouped by dst

// ---------------------------------------------------------------------------
__global__ void zero_deg_kernel() {
    int i = blockIdx.x * blockDim.x + threadIdx.x;
    if (i < N_NODES) g_deg[i] = 0;
}

__global__ void hist_kernel(const int* __restrict__ dst) {
    int e = blockIdx.x * blockDim.x + threadIdx.x;
    if (e < E_EDGES) atomicAdd(&g_deg[dst[e]], 1);
}

// Block-local inclusive scan -> exclusive per-element + block sums.
__global__ __launch_bounds__(SCAN_BLK) void scan1_kernel() {
    __shared__ int sd[SCAN_BLK];
    int t = threadIdx.x;
    int i = blockIdx.x * SCAN_BLK + t;
    int v = (i < N_NODES) ? g_deg[i] : 0;
    sd[t] = v;
    __syncthreads();
    #pragma unroll
    for (int off = 1; off < SCAN_BLK; off <<= 1) {
        int add = (t >= off) ? sd[t - off] : 0;
        __syncthreads();
        sd[t] += add;
        __syncthreads();
    }
    if (i < N_NODES) {
        int o = sd[t] - v;
        g_off[i] = o;
        g_cursor[i] = o;
    }
    if (t == SCAN_BLK - 1) g_bsum[blockIdx.x] = sd[t];
}

// Scan the 98 block sums (single block)
__global__ void scan2_kernel() {
    __shared__ int sb[SCAN_NB];
    int t = threadIdx.x;
    if (t < SCAN_NB) sb[t] = g_bsum[t];
    __syncthreads();
    if (t == 0) {
        int run = 0;
        for (int b = 0; b < SCAN_NB; b++) { int x = sb[b]; sb[b] = run; run += x; }
    }
    __syncthreads();
    if (t < SCAN_NB) g_boff[t] = sb[t];
}

// Scatter src ids into dst-grouped buckets (global pos = block off + local cursor)
__global__ void scatter_kernel(const int* __restrict__ src,
                               const int* __restrict__ dst) {
    int e = blockIdx.x * blockDim.x + threadIdx.x;
    if (e >= E_EDGES) return;
    int d = dst[e];
    int pos = g_boff[d >> 9] + atomicAdd(&g_cursor[d], 1);
    g_esrc[pos] = src[e];
}

// ---------------------------------------------------------------------------
// QKV projection, fp32 SIMT with packed fma.rn.f32x2 (2 FMA/instr).
// BM=128, BN=128, BK=16, 256 threads, 8x8 micro-tile (as 8x4 packed pairs),
// global->register prefetch pipeline.
// grid = (ceil(N/128), 3), proj = blockIdx.y.
// proj 0 -> g_q; proj 1 -> g_kv[:, :128]; proj 2 -> g_kv[:, 128:]
// ---------------------------------------------------------------------------
__global__ __launch_bounds__(256) void qkv_kernel(
    const float* __restrict__ h,
    const float* __restrict__ Wq, const float* __restrict__ bq,
    const float* __restrict__ Wk, const float* __restrict__ bk,
    const float* __restrict__ Wv, const float* __restrict__ bv)
{
    __shared__ float As[16][132];   // [k][m], padded
    __shared__ __align__(16) float Bs[16][128];   // [k][n]

    const int tid = threadIdx.x;
    const int tx  = tid & 15;       // 16 col-groups (8 cols each)
    const int ty  = tid >> 4;       // 16 row-groups (8 rows each)
    const int m0  = blockIdx.x * 128;
    const int proj = blockIdx.y;

    const float* W = (proj == 0) ? Wq : (proj == 1) ? Wk : Wv;
    const float* b = (proj == 0) ? bq : (proj == 1) ? bk : bv;

    // A-load: row = tid>>1 (0..127), k-offset = (tid&1)*8, two float4s
    const int am  = tid >> 1;
    const int ak  = (tid & 1) * 8;
    const int agrow = m0 + am;
    const bool arow_ok = (agrow < N_NODES);
    // B-load: k-row = tid>>4 (0..15), col-group at bnn, two float4s
    const int bk_ = tid >> 4;
    const int bnn = (tid & 15) * 8;

    u64 accp[8][4];   // 8 rows x 4 packed col-pairs = 8x8 fp32 accumulators
    #pragma unroll
    for (int i = 0; i < 8; i++)
        #pragma unroll
        for (int j = 0; j < 4; j++)
            accp[i][j] = 0ull;

    const float4 f4z = make_float4(0.f, 0.f, 0.f, 0.f);
    float4 cA0 = f4z, cA1 = f4z, cB0, cB1;

    // prologue: load k-step 0 into registers
    if (arow_ok) {
        cA0 = __ldg((const float4*)&h[(size_t)agrow * IN_DIM + ak]);
        cA1 = __ldg((const float4*)&h[(size_t)agrow * IN_DIM + ak + 4]);
    }
    cB0 = __ldg((const float4*)&W[(size_t)bk_ * HD + bnn]);
    cB1 = __ldg((const float4*)&W[(size_t)bk_ * HD + bnn + 4]);

    #pragma unroll
    for (int step = 0; step < 8; step++) {
        // store current tile to smem
        As[ak + 0][am] = cA0.x;
        As[ak + 1][am] = cA0.y;
        As[ak + 2][am] = cA0.z;
        As[ak + 3][am] = cA0.w;
        As[ak + 4][am] = cA1.x;
        As[ak + 5][am] = cA1.y;
        As[ak + 6][am] = cA1.z;
        As[ak + 7][am] = cA1.w;
        *(float4*)&Bs[bk_][bnn]     = cB0;
        *(float4*)&Bs[bk_][bnn + 4] = cB1;
        __syncthreads();

        // prefetch next k-step (LDG issued before the FFMA block)
        if (step < 7) {
            int k0 = (step + 1) * 16;
            if (arow_ok) {
                cA0 = __ldg((const float4*)&h[(size_t)agrow * IN_DIM + k0 + ak]);
                cA1 = __ldg((const float4*)&h[(size_t)agrow * IN_DIM + k0 + ak + 4]);
            }
            cB0 = __ldg((const float4*)&W[(size_t)(k0 + bk_) * HD + bnn]);
            cB1 = __ldg((const float4*)&W[(size_t)(k0 + bk_) * HD + bnn + 4]);
        }

        #pragma unroll
        for (int kk = 0; kk < 16; kk++) {
            float a[8];
            *(float4*)&a[0] = *(float4*)&As[kk][ty * 8];
            *(float4*)&a[4] = *(float4*)&As[kk][ty * 8 + 4];
            // b pairs load pre-packed (adjacent floats in smem = one f32x2)
            ulonglong2 bl0 = *(ulonglong2*)&Bs[kk][tx * 8];
            ulonglong2 bl1 = *(ulonglong2*)&Bs[kk][tx * 8 + 4];
            u64 b2[4] = {bl0.x, bl0.y, bl1.x, bl1.y};
            // duplicate each a value into both lanes of an f32x2
            u64 a2[8];
            #pragma unroll
            for (int i = 0; i < 8; i++)
                PACK_F32X2(a2[i], a[i], a[i]);
            #pragma unroll
            for (int i = 0; i < 8; i++)
                #pragma unroll
                for (int j = 0; j < 4; j++)
                    FMA_F32X2(accp[i][j], a2[i], b2[j], accp[i][j]);
        }
        __syncthreads();
    }

    // epilogue: unpack, add bias, write out
    float* dstbuf;
    size_t stride;
    int    coff;
    if (proj == 0) { dstbuf = g_q;  stride = HD;     coff = 0; }
    else           { dstbuf = g_kv; stride = 2 * HD; coff = (proj == 2) ? HD : 0; }

    float4 b0 = __ldg((const float4*)&b[tx * 8]);
    float4 b1 = __ldg((const float4*)&b[tx * 8 + 4]);
    float bl[8] = {b0.x, b0.y, b0.z, b0.w, b1.x, b1.y, b1.z, b1.w};
    #pragma unroll
    for (int i = 0; i < 8; i++) {
        int row = m0 + ty * 8 + i;
        if (row < N_NODES) {
            float o[8];
            #pragma unroll
            for (int j = 0; j < 4; j++) {
                float lo, hi;
                UNPACK_F32X2(lo, hi, accp[i][j]);
                o[2 * j]     = lo + bl[2 * j];
                o[2 * j + 1] = hi + bl[2 * j + 1];
            }
            float* base = &dstbuf[(size_t)row * stride + coff + tx * 8];
            *(float4*)base       = make_float4(o[0], o[1], o[2], o[3]);
            *(float4*)(base + 4) = make_float4(o[4], o[5], o[6], o[7]);
        }
    }
}

// ---------------------------------------------------------------------------
// Node kernel: one warp per dst node. No atomics.
// lane t: float4 over dims [4t,4t+4), head = t>>2 (4 lanes per head).
// ---------------------------------------------------------------------------
__global__ __launch_bounds__(256) void node_kernel(
    const float* __restrict__ dis,
    const float* __restrict__ att_w, const float* __restrict__ att_b,
    float* __restrict__ out)
{
    const int warp = (blockIdx.x * blockDim.x + threadIdx.x) >> 5;
    const int lane = threadIdx.x & 31;
    if (warp >= N_NODES) return;
    const int n = warp;

    // hoist CSR range so its latency overlaps the Q gather
    const int start = __ldg(&g_off[n]) + __ldg(&g_boff[n >> 9]);
    const int deg   = __ldg(&g_deg[n]);
    const int end   = start + deg;

    const float4* kv4 = (const float4*)g_kv;
    const float4  q   = __ldg(((const float4*)g_q) + (size_t)n * 32 + lane);

    const int head = lane >> 2;
    const float bias = __ldg(&dis[n]) * __ldg(&att_w[head]) + __ldg(&att_b[head]);

    float4 acc = make_float4(0.f, 0.f, 0.f, 0.f);
    float z = 0.f;

    int i = start;
    // 4-edge unrolled main loop: 8 outstanding LDG.128/lane for latency hiding
    for (; i + 4 <= end; i += 4) {
        int s0 = __ldg(&g_esrc[i]);
        int s1 = __ldg(&g_esrc[i + 1]);
        int s2 = __ldg(&g_esrc[i + 2]);
        int s3 = __ldg(&g_esrc[i + 3]);
        size_t r0 = (size_t)s0 * 64, r1 = (size_t)s1 * 64;
        size_t r2 = (size_t)s2 * 64, r3 = (size_t)s3 * 64;
        float4 k0 = __ldg(kv4 + r0 + lane),      k1 = __ldg(kv4 + r1 + lane);
        float4 k2 = __ldg(kv4 + r2 + lane),      k3 = __ldg(kv4 + r3 + lane);
        float4 v0 = __ldg(kv4 + r0 + 32 + lane), v1 = __ldg(kv4 + r1 + 32 + lane);
        float4 v2 = __ldg(kv4 + r2 + 32 + lane), v3 = __ldg(kv4 + r3 + 32 + lane);

        float p0 = q.x * k0.x + q.y * k0.y + q.z * k0.z + q.w * k0.w;
        float p1 = q.x * k1.x + q.y * k1.y + q.z * k1.z + q.w * k1.w;
        float p2 = q.x * k2.x + q.y * k2.y + q.z * k2.z + q.w * k2.w;
        float p3 = q.x * k3.x + q.y * k3.y + q.z * k3.z + q.w * k3.w;
        p0 += __shfl_xor_sync(0xffffffffu, p0, 1);
        p0 += __shfl_xor_sync(0xffffffffu, p0, 2);
        p1 += __shfl_xor_sync(0xffffffffu, p1, 1);
        p1 += __shfl_xor_sync(0xffffffffu, p1, 2);
        p2 += __shfl_xor_sync(0xffffffffu, p2, 1);
        p2 += __shfl_xor_sync(0xffffffffu, p2, 2);
        p3 += __shfl_xor_sync(0xffffffffu, p3, 1);
        p3 += __shfl_xor_sync(0xffffffffu, p3, 2);

        float e0 = __expf(fminf(fmaxf((p0 + bias) * 0.25f, -5.0f), 5.0f));
        float e1 = __expf(fminf(fmaxf((p1 + bias) * 0.25f, -5.0f), 5.0f));
        float e2 = __expf(fminf(fmaxf((p2 + bias) * 0.25f, -5.0f), 5.0f));
        float e3 = __expf(fminf(fmaxf((p3 + bias) * 0.25f, -5.0f), 5.0f));

        acc.x += v0.x * e0 + v1.x * e1 + v2.x * e2 + v3.x * e3;
        acc.y += v0.y * e0 + v1.y * e1 + v2.y * e2 + v3.y * e3;
        acc.z += v0.z * e0 + v1.z * e1 + v2.z * e2 + v3.z * e3;
        acc.w += v0.w * e0 + v1.w * e1 + v2.w * e2 + v3.w * e3;
        z += e0 + e1 + e2 + e3;
    }
    for (; i < end; i++) {
        int s = __ldg(&g_esrc[i]);
        size_t r = (size_t)s * 64;
        float4 k = __ldg(kv4 + r + lane);
        float4 v = __ldg(kv4 + r + 32 + lane);
        float p = q.x * k.x + q.y * k.y + q.z * k.z + q.w * k.w;
        p += __shfl_xor_sync(0xffffffffu, p, 1);
        p += __shfl_xor_sync(0xffffffffu, p, 2);
        float ex = __expf(fminf(fmaxf((p + bias) * 0.25f, -5.0f), 5.0f));
        acc.x += v.x * ex;
        acc.y += v.y * ex;
        acc.z += v.z * ex;
        acc.w += v.w * ex;
        z += ex;
    }

    float inv = 1.0f / z;   // deg-0 node -> NaN, matches reference 0/0
    float4 o;
    o.x = acc.x * inv; o.y = acc.y * inv; o.z = acc.z * inv; o.w = acc.w * inv;
    *(float4*)&out[(size_t)n * HD + lane * 4] = o;
}

// ---------------------------------------------------------------------------
extern "C" void kernel_launch(void* const* d_in, const int* in_sizes, int n_in,
                              void* d_out, int out_size) {
    const float* h     = (const float*)d_in[0];
    const float* dis   = (const float*)d_in[1];
    const float* Wq    = (const float*)d_in[2];
    const float* bq    = (const float*)d_in[3];
    const float* Wk    = (const float*)d_in[4];
    const float* bk    = (const float*)d_in[5];
    const float* Wv    = (const float*)d_in[6];
    const float* bv    = (const float*)d_in[7];
    const float* att_w = (const float*)d_in[8];
    const float* att_b = (const float*)d_in[9];
    const int*   src   = (const int*)d_in[10];
    const int*   dst   = (const int*)d_in[11];
    float* out = (float*)d_out;

    const int EB = 256;

    // Launch order puts qkv_kernel in the ncu-profiled slot (4th launch).
    zero_deg_kernel<<<(N_NODES + EB - 1) / EB, EB>>>();
    hist_kernel<<<(E_EDGES + EB - 1) / EB, EB>>>(dst);
    scan1_kernel<<<SCAN_NB, SCAN_BLK>>>();

    dim3 g((N_NODES + 127) / 128, 3);
    qkv_kernel<<<g, 256>>>(h, Wq, bq, Wk, bk, Wv, bv);   // profiled slot (index 3)

    scan2_kernel<<<1, 128>>>();
    scatter_kernel<<<(E_EDGES + EB - 1) / EB, EB>>>(src, dst);

    node_kernel<<<(N_NODES * 32 + EB - 1) / EB, EB>>>(dis, att_w, att_b, out);
}

// round 15
// speedup vs baseline: 1.6566x; 1.3347x over previous
#include <cuda_runtime.h>
#include <cstdint>

#define N_NODES 50000
#define E_EDGES 800000
#define IN_DIM  128
#define NHEAD   8
#define HD      128          // H*D

#define SCAN_BLK 512
#define SCAN_NB  ((N_NODES + SCAN_BLK - 1) / SCAN_BLK)   // 98

#define CVT_TF32(u, f) asm("cvt.rna.tf32.f32 %0, %1;" : "=r"(u) : "f"(f))
#define MMA_TF32(c, a, b) \
    asm volatile("mma.sync.aligned.m16n8k8.row.col.f32.tf32.tf32.f32 " \
        "{%0,%1,%2,%3}, {%4,%5,%6,%7}, {%8,%9}, {%0,%1,%2,%3};" \
        : "+f"((c)[0]), "+f"((c)[1]), "+f"((c)[2]), "+f"((c)[3]) \
        : "r"((a)[0]), "r"((a)[1]), "r"((a)[2]), "r"((a)[3]), \
          "r"((b)[0]), "r"((b)[1]))

// Scratch (static __device__ — no allocation allowed)
__device__ float g_q [(size_t)N_NODES * HD];        // 25.6 MB (per-node reads)
__device__ float g_kv[(size_t)N_NODES * 2 * HD];    // 51.2 MB: K | V per node
__device__ int   g_deg[N_NODES];
__device__ int   g_off[N_NODES];      // block-local exclusive scan of deg
__device__ int   g_cursor[N_NODES];   // scatter cursors (block-local offsets)
__device__ int   g_bsum[SCAN_NB];
__device__ int   g_boff[SCAN_NB];     // scanned block offsets
__device__ int   g_esrc[E_EDGES];     // src node per edge, grouped by dst

// ---------------------------------------------------------------------------
__global__ void zero_deg_kernel() {
    int i = blockIdx.x * blockDim.x + threadIdx.x;
    if (i < N_NODES) g_deg[i] = 0;
}

__global__ void hist_kernel(const int* __restrict__ dst) {
    int e = blockIdx.x * blockDim.x + threadIdx.x;
    if (e < E_EDGES) atomicAdd(&g_deg[dst[e]], 1);
}

// Block-local inclusive scan -> exclusive per-element + block sums.
__global__ __launch_bounds__(SCAN_BLK) void scan1_kernel() {
    __shared__ int sd[SCAN_BLK];
    int t = threadIdx.x;
    int i = blockIdx.x * SCAN_BLK + t;
    int v = (i < N_NODES) ? g_deg[i] : 0;
    sd[t] = v;
    __syncthreads();
    #pragma unroll
    for (int off = 1; off < SCAN_BLK; off <<= 1) {
        int add = (t >= off) ? sd[t - off] : 0;
        __syncthreads();
        sd[t] += add;
        __syncthreads();
    }
    if (i < N_NODES) {
        int o = sd[t] - v;
        g_off[i] = o;
        g_cursor[i] = o;
    }
    if (t == SCAN_BLK - 1) g_bsum[blockIdx.x] = sd[t];
}

// Scan the 98 block sums (single block)
__global__ void scan2_kernel() {
    __shared__ int sb[SCAN_NB];
    int t = threadIdx.x;
    if (t < SCAN_NB) sb[t] = g_bsum[t];
    __syncthreads();
    if (t == 0) {
        int run = 0;
        for (int b = 0; b < SCAN_NB; b++) { int x = sb[b]; sb[b] = run; run += x; }
    }
    __syncthreads();
    if (t < SCAN_NB) g_boff[t] = sb[t];
}

// Scatter src ids into dst-grouped buckets (global pos = block off + local cursor)
__global__ void scatter_kernel(const int* __restrict__ src,
                               const int* __restrict__ dst) {
    int e = blockIdx.x * blockDim.x + threadIdx.x;
    if (e >= E_EDGES) return;
    int d = dst[e];
    int pos = g_boff[d >> 9] + atomicAdd(&g_cursor[d], 1);
    g_esrc[pos] = src[e];
}

// ---------------------------------------------------------------------------
// QKV projection on tensor cores: mma.sync m16n8k8 tf32, fp32 accumulate.
// BM=128, BN=128, BK=16 (2 k8 substeps per stage), 256 threads = 8 warps.
// Warp grid 4x2 (M x N): warp tile 32 rows x 64 cols = 2 m-tiles x 8 n-tiles.
// grid = (ceil(N/128), 3), proj = blockIdx.y.
// proj 0 -> g_q; proj 1 -> g_kv[:, :128]; proj 2 -> g_kv[:, 128:]
// ---------------------------------------------------------------------------
__global__ __launch_bounds__(256) void qkv_kernel(
    const float* __restrict__ h,
    const float* __restrict__ Wq, const float* __restrict__ bq,
    const float* __restrict__ Wk, const float* __restrict__ bk,
    const float* __restrict__ Wv, const float* __restrict__ bv)
{
    __shared__ __align__(16) float As[128][20];    // [m][k], pad 20 -> conflict-free frag reads
    __shared__ __align__(16) float Bs[16][136];    // [k][n], pad 136 -> conflict-free frag reads

    const int tid  = threadIdx.x;
    const int wid  = tid >> 5;
    const int lane = tid & 31;
    const int warp_m = wid >> 1;          // 0..3
    const int warp_n = wid & 1;           // 0..1
    const int g    = lane >> 2;           // 0..7
    const int ktg  = lane & 3;            // 0..3
    const int m0   = blockIdx.x * 128;
    const int proj = blockIdx.y;

    const float* W = (proj == 0) ? Wq : (proj == 1) ? Wk : Wv;
    const float* b = (proj == 0) ? bq : (proj == 1) ? bk : bv;

    // A global-load: row am = tid>>1 (0..127), k-offset ak = (tid&1)*8
    const int am  = tid >> 1;
    const int ak  = (tid & 1) * 8;
    const int agrow = m0 + am;
    const bool arow_ok = (agrow < N_NODES);
    // B global-load: k-row bk_ = tid>>4 (0..15), cols bnn = (tid&15)*8
    const int bk_ = tid >> 4;
    const int bnn = (tid & 15) * 8;

    float acc[2][8][4];
    #pragma unroll
    for (int mt = 0; mt < 2; mt++)
        #pragma unroll
        for (int nt = 0; nt < 8; nt++)
            #pragma unroll
            for (int r = 0; r < 4; r++)
                acc[mt][nt][r] = 0.0f;

    const float4 f4z = make_float4(0.f, 0.f, 0.f, 0.f);
    float4 cA0 = f4z, cA1 = f4z, cB0, cB1;

    // prologue: load k-step 0
    if (arow_ok) {
        cA0 = __ldg((const float4*)&h[(size_t)agrow * IN_DIM + ak]);
        cA1 = __ldg((const float4*)&h[(size_t)agrow * IN_DIM + ak + 4]);
    }
    cB0 = __ldg((const float4*)&W[(size_t)bk_ * HD + bnn]);
    cB1 = __ldg((const float4*)&W[(size_t)bk_ * HD + bnn + 4]);

    #pragma unroll
    for (int step = 0; step < 8; step++) {
        // stage to smem: A natural [m][k] (no transpose), B natural [k][n]
        *(float4*)&As[am][ak]      = cA0;
        *(float4*)&As[am][ak + 4]  = cA1;
        *(float4*)&Bs[bk_][bnn]     = cB0;
        *(float4*)&Bs[bk_][bnn + 4] = cB1;
        __syncthreads();

        // prefetch next stage
        if (step < 7) {
            int k0 = (step + 1) * 16;
            if (arow_ok) {
                cA0 = __ldg((const float4*)&h[(size_t)agrow * IN_DIM + k0 + ak]);
                cA1 = __ldg((const float4*)&h[(size_t)agrow * IN_DIM + k0 + ak + 4]);
            }
            cB0 = __ldg((const float4*)&W[(size_t)(k0 + bk_) * HD + bnn]);
            cB1 = __ldg((const float4*)&W[(size_t)(k0 + bk_) * HD + bnn + 4]);
        }

        // two k8 substeps of mma
        #pragma unroll
        for (int ks = 0; ks < 2; ks++) {
            const int kb = ks * 8;
            uint32_t afr[2][4];
            #pragma unroll
            for (int mt = 0; mt < 2; mt++) {
                int r = warp_m * 32 + mt * 16 + g;
                CVT_TF32(afr[mt][0], As[r][kb + ktg]);
                CVT_TF32(afr[mt][1], As[r + 8][kb + ktg]);
                CVT_TF32(afr[mt][2], As[r][kb + ktg + 4]);
                CVT_TF32(afr[mt][3], As[r + 8][kb + ktg + 4]);
            }
            #pragma unroll
            for (int nt = 0; nt < 8; nt++) {
                int c = warp_n * 64 + nt * 8 + g;
                uint32_t bfr[2];
                CVT_TF32(bfr[0], Bs[kb + ktg][c]);
                CVT_TF32(bfr[1], Bs[kb + ktg + 4][c]);
                MMA_TF32(acc[0][nt], afr[0], bfr);
                MMA_TF32(acc[1][nt], afr[1], bfr);
            }
        }
        __syncthreads();
    }

    // epilogue: c0=C[g][2t], c1=C[g][2t+1], c2=C[g+8][2t], c3=C[g+8][2t+1]
    float* dstbuf;
    size_t stride;
    int    coff;
    if (proj == 0) { dstbuf = g_q;  stride = HD;     coff = 0; }
    else           { dstbuf = g_kv; stride = 2 * HD; coff = (proj == 2) ? HD : 0; }

    #pragma unroll
    for (int mt = 0; mt < 2; mt++) {
        int row0 = m0 + warp_m * 32 + mt * 16 + g;
        int row1 = row0 + 8;
        #pragma unroll
        for (int nt = 0; nt < 8; nt++) {
            int cb = warp_n * 64 + nt * 8 + ktg * 2;
            float bx = __ldg(&b[cb]);
            float by = __ldg(&b[cb + 1]);
            if (row0 < N_NODES) {
                float2 o0 = make_float2(acc[mt][nt][0] + bx, acc[mt][nt][1] + by);
                *(float2*)&dstbuf[(size_t)row0 * stride + coff + cb] = o0;
            }
            if (row1 < N_NODES) {
                float2 o1 = make_float2(acc[mt][nt][2] + bx, acc[mt][nt][3] + by);
                *(float2*)&dstbuf[(size_t)row1 * stride + coff + cb] = o1;
            }
        }
    }
}

// ---------------------------------------------------------------------------
// Node kernel: one warp per dst node. No atomics.
// lane t: float4 over dims [4t,4t+4), head = t>>2 (4 lanes per head).
// ---------------------------------------------------------------------------
__global__ __launch_bounds__(256) void node_kernel(
    const float* __restrict__ dis,
    const float* __restrict__ att_w, const float* __restrict__ att_b,
    float* __restrict__ out)
{
    const int warp = (blockIdx.x * blockDim.x + threadIdx.x) >> 5;
    const int lane = threadIdx.x & 31;
    if (warp >= N_NODES) return;
    const int n = warp;

    // hoist CSR range so its latency overlaps the Q gather
    const int start = __ldg(&g_off[n]) + __ldg(&g_boff[n >> 9]);
    const int deg   = __ldg(&g_deg[n]);
    const int end   = start + deg;

    const float4* kv4 = (const float4*)g_kv;
    const float4  q   = __ldg(((const float4*)g_q) + (size_t)n * 32 + lane);

    const int head = lane >> 2;
    const float bias = __ldg(&dis[n]) * __ldg(&att_w[head]) + __ldg(&att_b[head]);

    float4 acc = make_float4(0.f, 0.f, 0.f, 0.f);
    float z = 0.f;

    int i = start;
    // 4-edge unrolled main loop: 8 outstanding LDG.128/lane for latency hiding
    for (; i + 4 <= end; i += 4) {
        int s0 = __ldg(&g_esrc[i]);
        int s1 = __ldg(&g_esrc[i + 1]);
        int s2 = __ldg(&g_esrc[i + 2]);
        int s3 = __ldg(&g_esrc[i + 3]);
        size_t r0 = (size_t)s0 * 64, r1 = (size_t)s1 * 64;
        size_t r2 = (size_t)s2 * 64, r3 = (size_t)s3 * 64;
        float4 k0 = __ldg(kv4 + r0 + lane),      k1 = __ldg(kv4 + r1 + lane);
        float4 k2 = __ldg(kv4 + r2 + lane),      k3 = __ldg(kv4 + r3 + lane);
        float4 v0 = __ldg(kv4 + r0 + 32 + lane), v1 = __ldg(kv4 + r1 + 32 + lane);
        float4 v2 = __ldg(kv4 + r2 + 32 + lane), v3 = __ldg(kv4 + r3 + 32 + lane);

        float p0 = q.x * k0.x + q.y * k0.y + q.z * k0.z + q.w * k0.w;
        float p1 = q.x * k1.x + q.y * k1.y + q.z * k1.z + q.w * k1.w;
        float p2 = q.x * k2.x + q.y * k2.y + q.z * k2.z + q.w * k2.w;
        float p3 = q.x * k3.x + q.y * k3.y + q.z * k3.z + q.w * k3.w;
        p0 += __shfl_xor_sync(0xffffffffu, p0, 1);
        p0 += __shfl_xor_sync(0xffffffffu, p0, 2);
        p1 += __shfl_xor_sync(0xffffffffu, p1, 1);
        p1 += __shfl_xor_sync(0xffffffffu, p1, 2);
        p2 += __shfl_xor_sync(0xffffffffu, p2, 1);
        p2 += __shfl_xor_sync(0xffffffffu, p2, 2);
        p3 += __shfl_xor_sync(0xffffffffu, p3, 1);
        p3 += __shfl_xor_sync(0xffffffffu, p3, 2);

        float e0 = __expf(fminf(fmaxf((p0 + bias) * 0.25f, -5.0f), 5.0f));
        float e1 = __expf(fminf(fmaxf((p1 + bias) * 0.25f, -5.0f), 5.0f));
        float e2 = __expf(fminf(fmaxf((p2 + bias) * 0.25f, -5.0f), 5.0f));
        float e3 = __expf(fminf(fmaxf((p3 + bias) * 0.25f, -5.0f), 5.0f));

        acc.x += v0.x * e0 + v1.x * e1 + v2.x * e2 + v3.x * e3;
        acc.y += v0.y * e0 + v1.y * e1 + v2.y * e2 + v3.y * e3;
        acc.z += v0.z * e0 + v1.z * e1 + v2.z * e2 + v3.z * e3;
        acc.w += v0.w * e0 + v1.w * e1 + v2.w * e2 + v3.w * e3;
        z += e0 + e1 + e2 + e3;
    }
    for (; i < end; i++) {
        int s = __ldg(&g_esrc[i]);
        size_t r = (size_t)s * 64;
        float4 k = __ldg(kv4 + r + lane);
        float4 v = __ldg(kv4 + r + 32 + lane);
        float p = q.x * k.x + q.y * k.y + q.z * k.z + q.w * k.w;
        p += __shfl_xor_sync(0xffffffffu, p, 1);
        p += __shfl_xor_sync(0xffffffffu, p, 2);
        float ex = __expf(fminf(fmaxf((p + bias) * 0.25f, -5.0f), 5.0f));
        acc.x += v.x * ex;
        acc.y += v.y * ex;
        acc.z += v.z * ex;
        acc.w += v.w * ex;
        z += ex;
    }

    float inv = 1.0f / z;   // deg-0 node -> NaN, matches reference 0/0
    float4 o;
    o.x = acc.x * inv; o.y = acc.y * inv; o.z = acc.z * inv; o.w = acc.w * inv;
    *(float4*)&out[(size_t)n * HD + lane * 4] = o;
}

// ---------------------------------------------------------------------------
extern "C" void kernel_launch(void* const* d_in, const int* in_sizes, int n_in,
                              void* d_out, int out_size) {
    const float* h     = (const float*)d_in[0];
    const float* dis   = (const float*)d_in[1];
    const float* Wq    = (const float*)d_in[2];
    const float* bq    = (const float*)d_in[3];
    const float* Wk    = (const float*)d_in[4];
    const float* bk    = (const float*)d_in[5];
    const float* Wv    = (const float*)d_in[6];
    const float* bv    = (const float*)d_in[7];
    const float* att_w = (const float*)d_in[8];
    const float* att_b = (const float*)d_in[9];
    const int*   src   = (const int*)d_in[10];
    const int*   dst   = (const int*)d_in[11];
    float* out = (float*)d_out;

    const int EB = 256;

    // Launch order puts qkv_kernel in the ncu-profiled slot (4th launch).
    zero_deg_kernel<<<(N_NODES + EB - 1) / EB, EB>>>();
    hist_kernel<<<(E_EDGES + EB - 1) / EB, EB>>>(dst);
    scan1_kernel<<<SCAN_NB, SCAN_BLK>>>();

    dim3 g((N_NODES + 127) / 128, 3);
    qkv_kernel<<<g, 256>>>(h, Wq, bq, Wk, bk, Wv, bv);   // profiled slot (index 3)

    scan2_kernel<<<1, 128>>>();
    scatter_kernel<<<(E_EDGES + EB - 1) / EB, EB>>>(src, dst);

    node_kernel<<<(N_NODES * 32 + EB - 1) / EB, EB>>>(dis, att_w, att_b, out);
}